// round 1
// baseline (speedup 1.0000x reference)
#include <cuda_runtime.h>
#include <cuda_bf16.h>

// ---------------- problem constants ----------------
#define T_LEN 2048
#define DM    1024
#define NHEAD 16
#define HDIM  64
#define NB    32      // number of key blocks (T/64)
#define SSEL  16      // selected blocks per token
#define NEGV  (-1e30f)

// ---------------- scratch (device globals; no allocs allowed) ----------------
__device__ float g_q   [T_LEN * DM];      // [t][h*64+d]
__device__ float g_k   [T_LEN * HDIM];    // [t][d]
__device__ float g_v   [T_LEN * HDIM];
__device__ float g_g   [T_LEN * 48];      // raw gate logits [t][h*3+j]
__device__ float g_kc  [NB * HDIM];       // pooled K blocks
__device__ float g_vc  [NB * HDIM];
__device__ float g_ocmp[T_LEN * DM];      // compressed-branch output
__device__ float g_comb[T_LEN * DM];      // gated combination (input to Wo GEMM)
__device__ int   g_blk [T_LEN * SSEL];    // selected block ids

// ---------------- big SGEMM: C[2048,1024] = A[2048,1024] * B[1024,1024]^T ----
// 128x128 tile, K-step 8, 256 threads, 8x8 microtile.
__global__ __launch_bounds__(256) void gemm_big(const float* __restrict__ A,
                                                const float* __restrict__ B,
                                                float* __restrict__ C) {
    __shared__ float As[8][128];
    __shared__ float Bs[8][128];
    const int tid = threadIdx.x;
    const int m0 = blockIdx.y * 128;
    const int n0 = blockIdx.x * 128;
    const int lr = tid >> 1;            // 0..127
    const int lc = (tid & 1) << 2;      // 0 or 4
    const int tx = tid & 15, ty = tid >> 4;
    const float* Ap = A + (m0 + lr) * 1024 + lc;
    const float* Bp = B + (n0 + lr) * 1024 + lc;

    float acc[8][8];
#pragma unroll
    for (int i = 0; i < 8; i++)
#pragma unroll
        for (int j = 0; j < 8; j++) acc[i][j] = 0.f;

    for (int k0 = 0; k0 < 1024; k0 += 8) {
        float4 a = *(const float4*)(Ap + k0);
        float4 b = *(const float4*)(Bp + k0);
        __syncthreads();
        As[lc + 0][lr] = a.x; As[lc + 1][lr] = a.y;
        As[lc + 2][lr] = a.z; As[lc + 3][lr] = a.w;
        Bs[lc + 0][lr] = b.x; Bs[lc + 1][lr] = b.y;
        Bs[lc + 2][lr] = b.z; Bs[lc + 3][lr] = b.w;
        __syncthreads();
#pragma unroll
        for (int kk = 0; kk < 8; kk++) {
            float ar[8], br[8];
            *(float4*)(ar)     = *(const float4*)&As[kk][ty * 8];
            *(float4*)(ar + 4) = *(const float4*)&As[kk][ty * 8 + 4];
            *(float4*)(br)     = *(const float4*)&Bs[kk][tx * 8];
            *(float4*)(br + 4) = *(const float4*)&Bs[kk][tx * 8 + 4];
#pragma unroll
            for (int i = 0; i < 8; i++)
#pragma unroll
                for (int j = 0; j < 8; j++) acc[i][j] += ar[i] * br[j];
        }
    }
#pragma unroll
    for (int i = 0; i < 8; i++) {
        float4 c0 = make_float4(acc[i][0], acc[i][1], acc[i][2], acc[i][3]);
        float4 c1 = make_float4(acc[i][4], acc[i][5], acc[i][6], acc[i][7]);
        float* cp = C + (size_t)(m0 + ty * 8 + i) * 1024 + n0 + tx * 8;
        *(float4*)(cp)     = c0;
        *(float4*)(cp + 4) = c1;
    }
}

// ---------------- small projections: K, V, G in one launch ------------------
// blockIdx.x in {0,1,2} selects weight/output; blockIdx.y tiles M by 64.
__global__ __launch_bounds__(256) void proj_small(const float* __restrict__ X,
                                                  const float* __restrict__ Wk,
                                                  const float* __restrict__ Wv,
                                                  const float* __restrict__ Wg) {
    const float* B; float* C; int N;
    if (blockIdx.x == 0)      { B = Wk; C = g_k; N = 64; }
    else if (blockIdx.x == 1) { B = Wv; C = g_v; N = 64; }
    else                      { B = Wg; C = g_g; N = 48; }

    __shared__ float As[16][68];
    __shared__ float Bs[16][68];
    const int tid = threadIdx.x;
    const int m0 = blockIdx.y * 64;
    const int lr = tid >> 2;          // 0..63
    const int lc = (tid & 3) << 2;    // 0,4,8,12
    const int tx = tid & 15, ty = tid >> 4;

    float acc[4][4];
#pragma unroll
    for (int i = 0; i < 4; i++)
#pragma unroll
        for (int j = 0; j < 4; j++) acc[i][j] = 0.f;

    for (int k0 = 0; k0 < 1024; k0 += 16) {
        float4 a = *(const float4*)(X + (size_t)(m0 + lr) * 1024 + k0 + lc);
        float4 b = (lr < N) ? *(const float4*)(B + (size_t)lr * 1024 + k0 + lc)
                            : make_float4(0.f, 0.f, 0.f, 0.f);
        __syncthreads();
        As[lc + 0][lr] = a.x; As[lc + 1][lr] = a.y;
        As[lc + 2][lr] = a.z; As[lc + 3][lr] = a.w;
        Bs[lc + 0][lr] = b.x; Bs[lc + 1][lr] = b.y;
        Bs[lc + 2][lr] = b.z; Bs[lc + 3][lr] = b.w;
        __syncthreads();
#pragma unroll
        for (int kk = 0; kk < 16; kk++) {
            float4 a4 = *(const float4*)&As[kk][ty * 4];
            float4 b4 = *(const float4*)&Bs[kk][tx * 4];
            float ar[4] = {a4.x, a4.y, a4.z, a4.w};
            float br[4] = {b4.x, b4.y, b4.z, b4.w};
#pragma unroll
            for (int i = 0; i < 4; i++)
#pragma unroll
                for (int j = 0; j < 4; j++) acc[i][j] += ar[i] * br[j];
        }
    }
#pragma unroll
    for (int i = 0; i < 4; i++) {
        int row = m0 + ty * 4 + i;
#pragma unroll
        for (int j = 0; j < 4; j++) {
            int col = tx * 4 + j;
            if (col < N) C[(size_t)row * N + col] = acc[i][j];
        }
    }
}

// ---------------- mean-pool K,V into 32 block summaries ---------------------
__global__ void pool_kv() {
    int c = blockIdx.x, d = threadIdx.x;   // 32 blocks, 64 threads
    float sk = 0.f, sv = 0.f;
    for (int i = 0; i < 64; i++) {
        sk += g_k[(size_t)(c * 64 + i) * 64 + d];
        sv += g_v[(size_t)(c * 64 + i) * 64 + d];
    }
    g_kc[c * 64 + d] = sk * (1.f / 64.f);
    g_vc[c * 64 + d] = sv * (1.f / 64.f);
}

// ---------------- compressed attention + top-k selection --------------------
__global__ __launch_bounds__(128) void cmp_kernel() {
    __shared__ float sq[1024];
    __shared__ float skc[NB * 64];
    __shared__ float svc[NB * 64];
    __shared__ float sp[NHEAD * NB];
    __shared__ float simp[NB];

    const int t = blockIdx.x, tid = threadIdx.x;
    // stage q (256 float4) and pooled K/V (512 float4 each)
    for (int i = tid; i < 256; i += 128)
        ((float4*)sq)[i] = ((const float4*)(g_q + (size_t)t * 1024))[i];
    for (int i = tid; i < 512; i += 128) {
        ((float4*)skc)[i] = ((const float4*)g_kc)[i];
        ((float4*)svc)[i] = ((const float4*)g_vc)[i];
    }
    __syncthreads();

    const int cur = t >> 6;
    const int nvis = (t + 1) >> 6;
    const float scale = 0.125f;  // 64^-0.5

    // scores [16 heads][32 blocks]
    for (int idx = tid; idx < NHEAD * NB; idx += 128) {
        int h = idx >> 5, c = idx & 31;
        float s;
        if (c < nvis) {
            const float4* qa = (const float4*)(sq + h * 64);
            const float4* ka = (const float4*)(skc + c * 64);
            s = 0.f;
#pragma unroll
            for (int i = 0; i < 16; i++) {
                float4 x = qa[i], y = ka[i];
                s += x.x * y.x + x.y * y.y + x.z * y.z + x.w * y.w;
            }
            s *= scale;
        } else s = NEGV;
        sp[idx] = s;
    }
    __syncthreads();

    // per-head softmax over visible blocks
    if (tid < NHEAD) {
        float* row = sp + tid * NB;
        if (nvis == 0) {
            for (int c = 0; c < NB; c++) row[c] = 0.f;
        } else {
            float m = -INFINITY;
            for (int c = 0; c < nvis; c++) m = fmaxf(m, row[c]);
            float sum = 0.f;
            for (int c = 0; c < nvis; c++) { float e = __expf(row[c] - m); row[c] = e; sum += e; }
            float inv = 1.f / sum;
            for (int c = 0; c < nvis; c++) row[c] *= inv;
            for (int c = nvis; c < NB; c++) row[c] = 0.f;
        }
    }
    __syncthreads();

    // o_cmp = p @ v_c
    for (int idx = tid; idx < NHEAD * HDIM; idx += 128) {
        int h = idx >> 6, d = idx & 63;
        float o = 0.f;
        for (int c = 0; c < nvis; c++) o += sp[h * NB + c] * svc[c * 64 + d];
        g_ocmp[(size_t)t * 1024 + idx] = o;
    }

    // importance per block (sum over heads), mask + force
    if (tid < NB) {
        int c = tid;
        float im;
        if (c == 0 || c == cur) im = INFINITY;
        else if (c <= cur) {
            im = 0.f;
            for (int h = 0; h < NHEAD; h++) im += sp[h * NB + c];
        } else im = NEGV;
        simp[c] = im;
    }
    __syncthreads();

    // stable top-16 (descending value, lowest index on tie) == jax.lax.top_k
    if (tid == 0) {
        unsigned used = 0;
        for (int s = 0; s < SSEL; s++) {
            float bv = -INFINITY; int bc = 0;
            for (int c = 0; c < NB; c++)
                if (!((used >> c) & 1u) && simp[c] > bv) { bv = simp[c]; bc = c; }
            used |= (1u << bc);
            g_blk[t * SSEL + s] = bc;
        }
    }
}

// ---------------- selected block-sparse attention + gated combine -----------
// one CTA per token, 256 threads (8 warps; warp w owns heads 2w, 2w+1).
// dynamic smem: sS[16*1024] | sQ[1024] | sK[64*68]
__global__ __launch_bounds__(256) void slc_kernel() {
    extern __shared__ float sm[];
    float* sS = sm;               // 16384 floats
    float* sQ = sm + 16384;       // 1024
    float* sK = sm + 17408;       // 64*68 = 4352
    __shared__ int sblk[SSEL];

    const int t = blockIdx.x, tid = threadIdx.x;
    if (tid < SSEL) sblk[tid] = g_blk[t * SSEL + tid];
    ((float4*)sQ)[tid] = ((const float4*)(g_q + (size_t)t * 1024))[tid];
    __syncthreads();

    const int w = tid >> 5, l = tid & 31;
    const int h0 = w * 2, h1 = w * 2 + 1;
    const float scale = 0.125f;

    // ---- phase 1: scores into sS (masked, scaled) ----
    for (int kb = 0; kb < SSEL; kb++) {
        int sb = sblk[kb];
        const float4* src = (const float4*)(g_k + (size_t)sb * 4096);
        __syncthreads();
#pragma unroll
        for (int i = 0; i < 4; i++) {
            int e = i * 256 + tid;          // float4 index in [0,1024)
            int j = e >> 4;
            int d4 = (e & 15) << 2;
            *(float4*)&sK[j * 68 + d4] = src[e];
        }
        __syncthreads();
        float s00 = 0.f, s01 = 0.f, s10 = 0.f, s11 = 0.f;
        const float4* q0 = (const float4*)(sQ + h0 * 64);
        const float4* q1 = (const float4*)(sQ + h1 * 64);
        const float4* ka = (const float4*)(sK + l * 68);
        const float4* kb4 = (const float4*)(sK + (l + 32) * 68);
#pragma unroll
        for (int d4 = 0; d4 < 16; d4++) {
            float4 qa = q0[d4], qb = q1[d4], x = ka[d4], y = kb4[d4];
            s00 += qa.x * x.x + qa.y * x.y + qa.z * x.z + qa.w * x.w;
            s01 += qa.x * y.x + qa.y * y.y + qa.z * y.z + qa.w * y.w;
            s10 += qb.x * x.x + qb.y * x.y + qb.z * x.z + qb.w * x.w;
            s11 += qb.x * y.x + qb.y * y.y + qb.z * y.z + qb.w * y.w;
        }
        int tokA = sb * 64 + l, tokB = tokA + 32;
        sS[h0 * 1024 + kb * 64 + l]      = (tokA <= t) ? s00 * scale : NEGV;
        sS[h0 * 1024 + kb * 64 + l + 32] = (tokB <= t) ? s01 * scale : NEGV;
        sS[h1 * 1024 + kb * 64 + l]      = (tokA <= t) ? s10 * scale : NEGV;
        sS[h1 * 1024 + kb * 64 + l + 32] = (tokB <= t) ? s11 * scale : NEGV;
    }

    // ---- phase 2: per-head softmax (warp-local; own heads only) ----
#pragma unroll
    for (int hp = 0; hp < 2; hp++) {
        int hh = h0 + hp;
        float vreg[32];
        float m = -INFINITY;
#pragma unroll
        for (int i = 0; i < 32; i++) {
            vreg[i] = sS[hh * 1024 + i * 32 + l];
            m = fmaxf(m, vreg[i]);
        }
#pragma unroll
        for (int off = 16; off >= 1; off >>= 1)
            m = fmaxf(m, __shfl_xor_sync(0xffffffffu, m, off));
        float sum = 0.f;
#pragma unroll
        for (int i = 0; i < 32; i++) {
            float e = __expf(vreg[i] - m);
            vreg[i] = e; sum += e;
        }
#pragma unroll
        for (int off = 16; off >= 1; off >>= 1)
            sum += __shfl_xor_sync(0xffffffffu, sum, off);
        float inv = 1.f / sum;
#pragma unroll
        for (int i = 0; i < 32; i++) sS[hh * 1024 + i * 32 + l] = vreg[i] * inv;
    }

    // ---- phase 3: O = P @ V_sel ----
    float a00 = 0.f, a01 = 0.f, a10 = 0.f, a11 = 0.f;
    for (int kb = 0; kb < SSEL; kb++) {
        int sb = sblk[kb];
        const float4* src = (const float4*)(g_v + (size_t)sb * 4096);
        __syncthreads();
#pragma unroll
        for (int i = 0; i < 4; i++) {
            int e = i * 256 + tid;
            int j = e >> 4;
            int d4 = (e & 15) << 2;
            *(float4*)&sK[j * 68 + d4] = src[e];
        }
        __syncthreads();
        const float4* p0 = (const float4*)(sS + h0 * 1024 + kb * 64);
        const float4* p1 = (const float4*)(sS + h1 * 1024 + kb * 64);
#pragma unroll
        for (int j4 = 0; j4 < 16; j4++) {
            float4 pa = p0[j4], pb = p1[j4];
            float par[4] = {pa.x, pa.y, pa.z, pa.w};
            float pbr[4] = {pb.x, pb.y, pb.z, pb.w};
#pragma unroll
            for (int jj = 0; jj < 4; jj++) {
                int j = j4 * 4 + jj;
                float va = sK[j * 68 + l];
                float vb = sK[j * 68 + l + 32];
                a00 += par[jj] * va; a01 += par[jj] * vb;
                a10 += pbr[jj] * va; a11 += pbr[jj] * vb;
            }
        }
    }

    // ---- epilogue: gates + compressed branch ----
    float gl0 = g_g[t * 48 + h0 * 3], gl0s = g_g[t * 48 + h0 * 3 + 1];
    float gl1 = g_g[t * 48 + h1 * 3], gl1s = g_g[t * 48 + h1 * 3 + 1];
    float gc0 = 1.f / (1.f + __expf(-gl0)), gs0 = 1.f / (1.f + __expf(-gl0s));
    float gc1 = 1.f / (1.f + __expf(-gl1)), gs1 = 1.f / (1.f + __expf(-gl1s));
    size_t o0 = (size_t)t * 1024 + h0 * 64 + l;
    size_t o1 = (size_t)t * 1024 + h1 * 64 + l;
    g_comb[o0]      = a00 * gs0 + g_ocmp[o0]      * gc0;
    g_comb[o0 + 32] = a01 * gs0 + g_ocmp[o0 + 32] * gc0;
    g_comb[o1]      = a10 * gs1 + g_ocmp[o1]      * gc1;
    g_comb[o1 + 32] = a11 * gs1 + g_ocmp[o1 + 32] * gc1;
}

// ---------------- launch ----------------------------------------------------
extern "C" void kernel_launch(void* const* d_in, const int* in_sizes, int n_in,
                              void* d_out, int out_size) {
    const float* x  = (const float*)d_in[0];
    const float* Wq = (const float*)d_in[1];
    const float* Wk = (const float*)d_in[2];
    const float* Wv = (const float*)d_in[3];
    const float* Wg = (const float*)d_in[4];
    const float* Wo = (const float*)d_in[5];
    float* out = (float*)d_out;

    void *pq = nullptr, *pcomb = nullptr;
    cudaGetSymbolAddress(&pq, g_q);
    cudaGetSymbolAddress(&pcomb, g_comb);

    const int slc_smem = (16384 + 1024 + 64 * 68) * 4;  // 87040 B
    cudaFuncSetAttribute(slc_kernel, cudaFuncAttributeMaxDynamicSharedMemorySize, slc_smem);

    gemm_big<<<dim3(8, 16), 256>>>(x, Wq, (float*)pq);
    proj_small<<<dim3(3, 32), 256>>>(x, Wk, Wv, Wg);
    pool_kv<<<NB, 64>>>();
    cmp_kernel<<<T_LEN, 128>>>();
    slc_kernel<<<T_LEN, 256, slc_smem>>>();
    gemm_big<<<dim3(8, 16), 256>>>((const float*)pcomb, Wo, out);
}

// round 3
// speedup vs baseline: 1.2876x; 1.2876x over previous
#include <cuda_runtime.h>
#include <cuda_bf16.h>
#include <cstdint>

// ---------------- problem constants ----------------
#define T_LEN 2048
#define DM    1024
#define NHEAD 16
#define HDIM  64
#define NB    32      // number of key blocks (T/64)
#define SSEL  16      // selected blocks per token
#define NEGV  (-1e30f)

// ---------------- scratch (device globals; no allocs allowed) ----------------
__device__ float g_q   [T_LEN * DM];      // [t][h*64+d]
__device__ float g_k   [T_LEN * HDIM];    // [t][d]
__device__ float g_v   [T_LEN * HDIM];
__device__ float g_g   [T_LEN * 48];      // raw gate logits [t][h*3+j]
__device__ float g_kc  [NB * HDIM];       // pooled K blocks
__device__ float g_vc  [NB * HDIM];
__device__ float g_ocmp[T_LEN * DM];      // compressed-branch output
__device__ float g_comb[T_LEN * DM];      // gated combination (input to Wo GEMM)
__device__ int   g_blk [T_LEN * SSEL];    // selected block ids

// bf16 hi/lo split copies for tensor-core GEMMs
__device__ __nv_bfloat16 g_xh [T_LEN * DM], g_xl [T_LEN * DM];
__device__ __nv_bfloat16 g_ch [T_LEN * DM], g_cl [T_LEN * DM];
__device__ __nv_bfloat16 g_wqh[DM * DM],   g_wql[DM * DM];
__device__ __nv_bfloat16 g_woh[DM * DM],   g_wol[DM * DM];

// ================= helpers ==================================================
__device__ __forceinline__ uint32_t smem_u32(const void* p) {
    uint32_t a;
    asm("{ .reg .u64 t; cvta.to.shared.u64 t, %1; cvt.u32.u64 %0, t; }"
        : "=r"(a) : "l"(p));
    return a;
}
__device__ __forceinline__ void cp_async16(uint32_t saddr, const void* gaddr) {
    asm volatile("cp.async.cg.shared.global [%0], [%1], 16;"
                 :: "r"(saddr), "l"(gaddr));
}
__device__ __forceinline__ void cp_commit() {
    asm volatile("cp.async.commit_group;" ::: "memory");
}
__device__ __forceinline__ void cp_wait0() {
    asm volatile("cp.async.wait_group 0;" ::: "memory");
}
__device__ __forceinline__ void ldsm4(uint32_t* r, uint32_t addr) {
    asm volatile("ldmatrix.sync.aligned.m8n8.x4.shared.b16 {%0,%1,%2,%3}, [%4];"
                 : "=r"(r[0]), "=r"(r[1]), "=r"(r[2]), "=r"(r[3]) : "r"(addr));
}
__device__ __forceinline__ void mma16816(float* d, const uint32_t* a, const uint32_t* b) {
    asm volatile(
        "mma.sync.aligned.m16n8k16.row.col.f32.bf16.bf16.f32 "
        "{%0,%1,%2,%3}, {%4,%5,%6,%7}, {%8,%9}, {%0,%1,%2,%3};"
        : "+f"(d[0]), "+f"(d[1]), "+f"(d[2]), "+f"(d[3])
        : "r"(a[0]), "r"(a[1]), "r"(a[2]), "r"(a[3]), "r"(b[0]), "r"(b[1]));
}

// ================= fp32 -> bf16 hi/lo conversion ============================
__global__ __launch_bounds__(256) void conv_hilo(const float4* __restrict__ src,
                                                 uint2* __restrict__ h,
                                                 uint2* __restrict__ l, int n4) {
    int i = blockIdx.x * 256 + threadIdx.x;
    if (i >= n4) return;
    float4 v = src[i];
    __nv_bfloat16 h0 = __float2bfloat16(v.x);
    __nv_bfloat16 h1 = __float2bfloat16(v.y);
    __nv_bfloat16 h2 = __float2bfloat16(v.z);
    __nv_bfloat16 h3 = __float2bfloat16(v.w);
    __nv_bfloat16 l0 = __float2bfloat16(v.x - __bfloat162float(h0));
    __nv_bfloat16 l1 = __float2bfloat16(v.y - __bfloat162float(h1));
    __nv_bfloat16 l2 = __float2bfloat16(v.z - __bfloat162float(h2));
    __nv_bfloat16 l3 = __float2bfloat16(v.w - __bfloat162float(h3));
    uint2 hv, lv;
    hv.x = (uint32_t)__bfloat16_as_ushort(h0) | ((uint32_t)__bfloat16_as_ushort(h1) << 16);
    hv.y = (uint32_t)__bfloat16_as_ushort(h2) | ((uint32_t)__bfloat16_as_ushort(h3) << 16);
    lv.x = (uint32_t)__bfloat16_as_ushort(l0) | ((uint32_t)__bfloat16_as_ushort(l1) << 16);
    lv.y = (uint32_t)__bfloat16_as_ushort(l2) | ((uint32_t)__bfloat16_as_ushort(l3) << 16);
    h[i] = hv;
    l[i] = lv;
}

// ================= tensor-core GEMM via mma.sync (bf16x3) ===================
// C[2048,1024] = (Ah+Al) @ (Bh+Bl)^T, dropping Al*Bl.
// 128x128 CTA tile, 8 warps (2x4), warp tile 64x32, K-chunk 32, cp.async 2-stage.
// smem tile layout: [128 rows][40 bf16] (80B row stride -> conflict-free ldmatrix).
#define TSTRIDE 80                      // bytes per smem row
#define TILE_BYTES (128 * TSTRIDE)      // 10240
#define BUF_BYTES  (4 * TILE_BYTES)     // Ah | Al | Bh | Bl
#define GEMM_SMEM  (2 * BUF_BYTES)      // 81920

__global__ __launch_bounds__(256) void gemm_mma(const __nv_bfloat16* __restrict__ Ah,
                                                const __nv_bfloat16* __restrict__ Al,
                                                const __nv_bfloat16* __restrict__ Bh,
                                                const __nv_bfloat16* __restrict__ Bl,
                                                float* __restrict__ C) {
    extern __shared__ char sm[];
    const uint32_t sbase = smem_u32(sm);
    const int tid = threadIdx.x;
    const int lane = tid & 31, wid = tid >> 5;
    const int m0 = blockIdx.y * 128;
    const int n0 = blockIdx.x * 128;
    const int wm = (wid >> 2) * 64;     // warp m-offset in tile
    const int wn = (wid & 3) * 32;      // warp n-offset in tile

    const __nv_bfloat16* gsrc[4] = {Ah, Al, Bh, Bl};

    float acc[4][4][4];
#pragma unroll
    for (int i = 0; i < 4; i++)
#pragma unroll
        for (int j = 0; j < 4; j++)
#pragma unroll
            for (int k = 0; k < 4; k++) acc[i][j][k] = 0.f;

    // ldmatrix source addresses (fixed per thread, vary by buffer/ks)
    const int arow = wm + (lane & 15);
    const int akc  = (lane >> 4) << 3;              // 0 or 8
    const int brow = wn + (lane & 7) + ((lane >> 4) << 3);
    const int bkc  = ((lane >> 3) & 1) << 3;

    auto issue = [&](int c, int buf) {
#pragma unroll
        for (int T = 0; T < 4; T++) {
            const __nv_bfloat16* src = gsrc[T];
            const int rb = (T < 2) ? m0 : n0;
#pragma unroll
            for (int i = 0; i < 2; i++) {
                int idx = i * 256 + tid;            // 0..511
                int row = idx >> 2;
                int u   = idx & 3;
                uint32_t sa = sbase + buf * BUF_BYTES + T * TILE_BYTES + row * TSTRIDE + u * 16;
                cp_async16(sa, src + (size_t)(rb + row) * 1024 + c * 32 + u * 8);
            }
        }
        cp_commit();
    };

    issue(0, 0);

    for (int c = 0; c < 32; c++) {
        const int buf = c & 1;
        cp_wait0();
        __syncthreads();
        if (c + 1 < 32) issue(c + 1, buf ^ 1);

        const uint32_t base = sbase + buf * BUF_BYTES;
#pragma unroll
        for (int ks = 0; ks < 2; ks++) {
            uint32_t ah[4][4], al[4][4], bh[2][4], bl[2][4];
#pragma unroll
            for (int mt = 0; mt < 4; mt++) {
                uint32_t aa = base + (arow + mt * 16) * TSTRIDE + (ks * 16 + akc) * 2;
                ldsm4(ah[mt], aa);
                ldsm4(al[mt], aa + TILE_BYTES);
            }
#pragma unroll
            for (int np = 0; np < 2; np++) {
                uint32_t ba = base + 2 * TILE_BYTES + (brow + np * 16) * TSTRIDE + (ks * 16 + bkc) * 2;
                ldsm4(bh[np], ba);
                ldsm4(bl[np], ba + TILE_BYTES);
            }
#pragma unroll
            for (int mt = 0; mt < 4; mt++)
#pragma unroll
                for (int nt = 0; nt < 4; nt++) {
                    const uint32_t* ph = &bh[nt >> 1][(nt & 1) * 2];
                    const uint32_t* pl = &bl[nt >> 1][(nt & 1) * 2];
                    mma16816(acc[mt][nt], ah[mt], ph);   // ah*bh
                    mma16816(acc[mt][nt], al[mt], ph);   // al*bh
                    mma16816(acc[mt][nt], ah[mt], pl);   // ah*bl
                }
        }
        __syncthreads();
    }

    // epilogue
    const int g = lane >> 2, t4 = lane & 3;
#pragma unroll
    for (int mt = 0; mt < 4; mt++)
#pragma unroll
        for (int nt = 0; nt < 4; nt++) {
            int r = m0 + wm + mt * 16 + g;
            int cc = n0 + wn + nt * 8 + t4 * 2;
            *(float2*)(C + (size_t)r * 1024 + cc)       = make_float2(acc[mt][nt][0], acc[mt][nt][1]);
            *(float2*)(C + (size_t)(r + 8) * 1024 + cc) = make_float2(acc[mt][nt][2], acc[mt][nt][3]);
        }
}

// ---------------- small projections: K, V, G in one launch ------------------
__global__ __launch_bounds__(256) void proj_small(const float* __restrict__ X,
                                                  const float* __restrict__ Wk,
                                                  const float* __restrict__ Wv,
                                                  const float* __restrict__ Wg) {
    const float* B; float* C; int N;
    if (blockIdx.x == 0)      { B = Wk; C = g_k; N = 64; }
    else if (blockIdx.x == 1) { B = Wv; C = g_v; N = 64; }
    else                      { B = Wg; C = g_g; N = 48; }

    __shared__ float As[16][68];
    __shared__ float Bs[16][68];
    const int tid = threadIdx.x;
    const int m0 = blockIdx.y * 64;
    const int lr = tid >> 2;          // 0..63
    const int lc = (tid & 3) << 2;    // 0,4,8,12
    const int tx = tid & 15, ty = tid >> 4;

    float acc[4][4];
#pragma unroll
    for (int i = 0; i < 4; i++)
#pragma unroll
        for (int j = 0; j < 4; j++) acc[i][j] = 0.f;

    for (int k0 = 0; k0 < 1024; k0 += 16) {
        float4 a = *(const float4*)(X + (size_t)(m0 + lr) * 1024 + k0 + lc);
        float4 b = (lr < N) ? *(const float4*)(B + (size_t)lr * 1024 + k0 + lc)
                            : make_float4(0.f, 0.f, 0.f, 0.f);
        __syncthreads();
        As[lc + 0][lr] = a.x; As[lc + 1][lr] = a.y;
        As[lc + 2][lr] = a.z; As[lc + 3][lr] = a.w;
        Bs[lc + 0][lr] = b.x; Bs[lc + 1][lr] = b.y;
        Bs[lc + 2][lr] = b.z; Bs[lc + 3][lr] = b.w;
        __syncthreads();
#pragma unroll
        for (int kk = 0; kk < 16; kk++) {
            float4 a4 = *(const float4*)&As[kk][ty * 4];
            float4 b4 = *(const float4*)&Bs[kk][tx * 4];
            float ar[4] = {a4.x, a4.y, a4.z, a4.w};
            float br[4] = {b4.x, b4.y, b4.z, b4.w};
#pragma unroll
            for (int i = 0; i < 4; i++)
#pragma unroll
                for (int j = 0; j < 4; j++) acc[i][j] += ar[i] * br[j];
        }
    }
#pragma unroll
    for (int i = 0; i < 4; i++) {
        int row = m0 + ty * 4 + i;
#pragma unroll
        for (int j = 0; j < 4; j++) {
            int col = tx * 4 + j;
            if (col < N) C[(size_t)row * N + col] = acc[i][j];
        }
    }
}

// ---------------- mean-pool K,V into 32 block summaries ---------------------
__global__ void pool_kv() {
    int c = blockIdx.x, d = threadIdx.x;   // 32 blocks, 64 threads
    float sk = 0.f, sv = 0.f;
    for (int i = 0; i < 64; i++) {
        sk += g_k[(size_t)(c * 64 + i) * 64 + d];
        sv += g_v[(size_t)(c * 64 + i) * 64 + d];
    }
    g_kc[c * 64 + d] = sk * (1.f / 64.f);
    g_vc[c * 64 + d] = sv * (1.f / 64.f);
}

// ---------------- compressed attention + top-k selection --------------------
__global__ __launch_bounds__(128) void cmp_kernel() {
    __shared__ float sq[1024];
    __shared__ float skc[NB * 64];
    __shared__ float svc[NB * 64];
    __shared__ float sp[NHEAD * NB];
    __shared__ float simp[NB];

    const int t = blockIdx.x, tid = threadIdx.x;
    for (int i = tid; i < 256; i += 128)
        ((float4*)sq)[i] = ((const float4*)(g_q + (size_t)t * 1024))[i];
    for (int i = tid; i < 512; i += 128) {
        ((float4*)skc)[i] = ((const float4*)g_kc)[i];
        ((float4*)svc)[i] = ((const float4*)g_vc)[i];
    }
    __syncthreads();

    const int cur = t >> 6;
    const int nvis = (t + 1) >> 6;
    const float scale = 0.125f;  // 64^-0.5

    for (int idx = tid; idx < NHEAD * NB; idx += 128) {
        int h = idx >> 5, c = idx & 31;
        float s;
        if (c < nvis) {
            const float4* qa = (const float4*)(sq + h * 64);
            const float4* ka = (const float4*)(skc + c * 64);
            s = 0.f;
#pragma unroll
            for (int i = 0; i < 16; i++) {
                float4 x = qa[i], y = ka[i];
                s += x.x * y.x + x.y * y.y + x.z * y.z + x.w * y.w;
            }
            s *= scale;
        } else s = NEGV;
        sp[idx] = s;
    }
    __syncthreads();

    if (tid < NHEAD) {
        float* row = sp + tid * NB;
        if (nvis == 0) {
            for (int c = 0; c < NB; c++) row[c] = 0.f;
        } else {
            float m = -INFINITY;
            for (int c = 0; c < nvis; c++) m = fmaxf(m, row[c]);
            float sum = 0.f;
            for (int c = 0; c < nvis; c++) { float e = __expf(row[c] - m); row[c] = e; sum += e; }
            float inv = 1.f / sum;
            for (int c = 0; c < nvis; c++) row[c] *= inv;
            for (int c = nvis; c < NB; c++) row[c] = 0.f;
        }
    }
    __syncthreads();

    for (int idx = tid; idx < NHEAD * HDIM; idx += 128) {
        int h = idx >> 6, d = idx & 63;
        float o = 0.f;
        for (int c = 0; c < nvis; c++) o += sp[h * NB + c] * svc[c * 64 + d];
        g_ocmp[(size_t)t * 1024 + idx] = o;
    }

    if (tid < NB) {
        int c = tid;
        float im;
        if (c == 0 || c == cur) im = INFINITY;
        else if (c <= cur) {
            im = 0.f;
            for (int h = 0; h < NHEAD; h++) im += sp[h * NB + c];
        } else im = NEGV;
        simp[c] = im;
    }
    __syncthreads();

    if (tid == 0) {
        unsigned used = 0;
        for (int s = 0; s < SSEL; s++) {
            float bv = -INFINITY; int bc = 0;
            for (int c = 0; c < NB; c++)
                if (!((used >> c) & 1u) && simp[c] > bv) { bv = simp[c]; bc = c; }
            used |= (1u << bc);
            g_blk[t * SSEL + s] = bc;
        }
    }
}

// ---------------- selected block-sparse attention + gated combine -----------
__global__ __launch_bounds__(256) void slc_kernel() {
    extern __shared__ float smf[];
    float* sS = smf;               // 16384 floats
    float* sQ = smf + 16384;       // 1024
    float* sK = smf + 17408;       // 64*68 = 4352
    __shared__ int sblk[SSEL];

    const int t = blockIdx.x, tid = threadIdx.x;
    if (tid < SSEL) sblk[tid] = g_blk[t * SSEL + tid];
    ((float4*)sQ)[tid] = ((const float4*)(g_q + (size_t)t * 1024))[tid];
    __syncthreads();

    const int w = tid >> 5, l = tid & 31;
    const int h0 = w * 2, h1 = w * 2 + 1;
    const float scale = 0.125f;

    for (int kb = 0; kb < SSEL; kb++) {
        int sb = sblk[kb];
        const float4* src = (const float4*)(g_k + (size_t)sb * 4096);
        __syncthreads();
#pragma unroll
        for (int i = 0; i < 4; i++) {
            int e = i * 256 + tid;
            int j = e >> 4;
            int d4 = (e & 15) << 2;
            *(float4*)&sK[j * 68 + d4] = src[e];
        }
        __syncthreads();
        float s00 = 0.f, s01 = 0.f, s10 = 0.f, s11 = 0.f;
        const float4* q0 = (const float4*)(sQ + h0 * 64);
        const float4* q1 = (const float4*)(sQ + h1 * 64);
        const float4* ka = (const float4*)(sK + l * 68);
        const float4* kb4 = (const float4*)(sK + (l + 32) * 68);
#pragma unroll
        for (int d4 = 0; d4 < 16; d4++) {
            float4 qa = q0[d4], qb = q1[d4], x = ka[d4], y = kb4[d4];
            s00 += qa.x * x.x + qa.y * x.y + qa.z * x.z + qa.w * x.w;
            s01 += qa.x * y.x + qa.y * y.y + qa.z * y.z + qa.w * y.w;
            s10 += qb.x * x.x + qb.y * x.y + qb.z * x.z + qb.w * x.w;
            s11 += qb.x * y.x + qb.y * y.y + qb.z * y.z + qb.w * y.w;
        }
        int tokA = sb * 64 + l, tokB = tokA + 32;
        sS[h0 * 1024 + kb * 64 + l]      = (tokA <= t) ? s00 * scale : NEGV;
        sS[h0 * 1024 + kb * 64 + l + 32] = (tokB <= t) ? s01 * scale : NEGV;
        sS[h1 * 1024 + kb * 64 + l]      = (tokA <= t) ? s10 * scale : NEGV;
        sS[h1 * 1024 + kb * 64 + l + 32] = (tokB <= t) ? s11 * scale : NEGV;
    }

#pragma unroll
    for (int hp = 0; hp < 2; hp++) {
        int hh = h0 + hp;
        float vreg[32];
        float m = -INFINITY;
#pragma unroll
        for (int i = 0; i < 32; i++) {
            vreg[i] = sS[hh * 1024 + i * 32 + l];
            m = fmaxf(m, vreg[i]);
        }
#pragma unroll
        for (int off = 16; off >= 1; off >>= 1)
            m = fmaxf(m, __shfl_xor_sync(0xffffffffu, m, off));
        float sum = 0.f;
#pragma unroll
        for (int i = 0; i < 32; i++) {
            float e = __expf(vreg[i] - m);
            vreg[i] = e; sum += e;
        }
#pragma unroll
        for (int off = 16; off >= 1; off >>= 1)
            sum += __shfl_xor_sync(0xffffffffu, sum, off);
        float inv = 1.f / sum;
#pragma unroll
        for (int i = 0; i < 32; i++) sS[hh * 1024 + i * 32 + l] = vreg[i] * inv;
    }

    float a00 = 0.f, a01 = 0.f, a10 = 0.f, a11 = 0.f;
    for (int kb = 0; kb < SSEL; kb++) {
        int sb = sblk[kb];
        const float4* src = (const float4*)(g_v + (size_t)sb * 4096);
        __syncthreads();
#pragma unroll
        for (int i = 0; i < 4; i++) {
            int e = i * 256 + tid;
            int j = e >> 4;
            int d4 = (e & 15) << 2;
            *(float4*)&sK[j * 68 + d4] = src[e];
        }
        __syncthreads();
        const float4* p0 = (const float4*)(sS + h0 * 1024 + kb * 64);
        const float4* p1 = (const float4*)(sS + h1 * 1024 + kb * 64);
#pragma unroll
        for (int j4 = 0; j4 < 16; j4++) {
            float4 pa = p0[j4], pb = p1[j4];
            float par[4] = {pa.x, pa.y, pa.z, pa.w};
            float pbr[4] = {pb.x, pb.y, pb.z, pb.w};
#pragma unroll
            for (int jj = 0; jj < 4; jj++) {
                int j = j4 * 4 + jj;
                float va = sK[j * 68 + l];
                float vb = sK[j * 68 + l + 32];
                a00 += par[jj] * va; a01 += par[jj] * vb;
                a10 += pbr[jj] * va; a11 += pbr[jj] * vb;
            }
        }
    }

    float gl0 = g_g[t * 48 + h0 * 3], gl0s = g_g[t * 48 + h0 * 3 + 1];
    float gl1 = g_g[t * 48 + h1 * 3], gl1s = g_g[t * 48 + h1 * 3 + 1];
    float gc0 = 1.f / (1.f + __expf(-gl0)), gs0 = 1.f / (1.f + __expf(-gl0s));
    float gc1 = 1.f / (1.f + __expf(-gl1)), gs1 = 1.f / (1.f + __expf(-gl1s));
    size_t o0 = (size_t)t * 1024 + h0 * 64 + l;
    size_t o1 = (size_t)t * 1024 + h1 * 64 + l;
    g_comb[o0]      = a00 * gs0 + g_ocmp[o0]      * gc0;
    g_comb[o0 + 32] = a01 * gs0 + g_ocmp[o0 + 32] * gc0;
    g_comb[o1]      = a10 * gs1 + g_ocmp[o1]      * gc1;
    g_comb[o1 + 32] = a11 * gs1 + g_ocmp[o1 + 32] * gc1;
}

// ---------------- launch ----------------------------------------------------
extern "C" void kernel_launch(void* const* d_in, const int* in_sizes, int n_in,
                              void* d_out, int out_size) {
    const float* x  = (const float*)d_in[0];
    const float* Wq = (const float*)d_in[1];
    const float* Wk = (const float*)d_in[2];
    const float* Wv = (const float*)d_in[3];
    const float* Wg = (const float*)d_in[4];
    const float* Wo = (const float*)d_in[5];
    float* out = (float*)d_out;

    void *pq, *pcomb, *pxh, *pxl, *pch, *pcl, *pwqh, *pwql, *pwoh, *pwol;
    cudaGetSymbolAddress(&pq, g_q);
    cudaGetSymbolAddress(&pcomb, g_comb);
    cudaGetSymbolAddress(&pxh, g_xh);   cudaGetSymbolAddress(&pxl, g_xl);
    cudaGetSymbolAddress(&pch, g_ch);   cudaGetSymbolAddress(&pcl, g_cl);
    cudaGetSymbolAddress(&pwqh, g_wqh); cudaGetSymbolAddress(&pwql, g_wql);
    cudaGetSymbolAddress(&pwoh, g_woh); cudaGetSymbolAddress(&pwol, g_wol);

    const int slc_smem = (16384 + 1024 + 64 * 68) * 4;  // 87040 B
    cudaFuncSetAttribute(slc_kernel, cudaFuncAttributeMaxDynamicSharedMemorySize, slc_smem);
    cudaFuncSetAttribute(gemm_mma, cudaFuncAttributeMaxDynamicSharedMemorySize, GEMM_SMEM);

    // split x, Wq, Wo into bf16 hi/lo
    conv_hilo<<<(T_LEN * DM / 4 + 255) / 256, 256>>>((const float4*)x, (uint2*)pxh, (uint2*)pxl, T_LEN * DM / 4);
    conv_hilo<<<(DM * DM / 4 + 255) / 256, 256>>>((const float4*)Wq, (uint2*)pwqh, (uint2*)pwql, DM * DM / 4);
    conv_hilo<<<(DM * DM / 4 + 255) / 256, 256>>>((const float4*)Wo, (uint2*)pwoh, (uint2*)pwol, DM * DM / 4);

    // Q = x @ Wq^T  (tensor cores via mma.sync, bf16x3)
    gemm_mma<<<dim3(8, 16), 256, GEMM_SMEM>>>((const __nv_bfloat16*)pxh, (const __nv_bfloat16*)pxl,
                                              (const __nv_bfloat16*)pwqh, (const __nv_bfloat16*)pwql,
                                              (float*)pq);
    proj_small<<<dim3(3, 32), 256>>>(x, Wk, Wv, Wg);
    pool_kv<<<NB, 64>>>();
    cmp_kernel<<<T_LEN, 128>>>();
    slc_kernel<<<T_LEN, 256, slc_smem>>>();

    // out = comb @ Wo^T  (tensor cores via mma.sync, bf16x3)
    conv_hilo<<<(T_LEN * DM / 4 + 255) / 256, 256>>>((const float4*)pcomb, (uint2*)pch, (uint2*)pcl, T_LEN * DM / 4);
    gemm_mma<<<dim3(8, 16), 256, GEMM_SMEM>>>((const __nv_bfloat16*)pch, (const __nv_bfloat16*)pcl,
                                              (const __nv_bfloat16*)pwoh, (const __nv_bfloat16*)pwol,
                                              out);
}

// round 4
// speedup vs baseline: 2.1705x; 1.6857x over previous
#include <cuda_runtime.h>
#include <cuda_bf16.h>
#include <cstdint>

// ---------------- problem constants ----------------
#define T_LEN 2048
#define DM    1024
#define NHEAD 16
#define HDIM  64
#define NB    32
#define SSEL  16
#define NEGV  (-1e30f)
#define NEGS  (-1.25e29f)   // NEGV * scale (0.125), finite

// ---------------- scratch ----------------------------------------------------
__device__ float g_q   [T_LEN * DM];
__device__ float g_k   [T_LEN * HDIM];
__device__ float g_v   [T_LEN * HDIM];
__device__ float g_g   [T_LEN * 48];
__device__ float g_kc  [NB * HDIM];
__device__ float g_vc  [NB * HDIM];
__device__ float g_ocmp[T_LEN * DM];
__device__ int   g_blk [T_LEN * SSEL];

__device__ __nv_bfloat16 g_xh [T_LEN * DM], g_xl [T_LEN * DM];
__device__ __nv_bfloat16 g_qh [T_LEN * DM], g_ql [T_LEN * DM];
__device__ __nv_bfloat16 g_ch [T_LEN * DM], g_cl [T_LEN * DM];
__device__ __nv_bfloat16 g_kh [T_LEN * HDIM], g_kl [T_LEN * HDIM];
__device__ __nv_bfloat16 g_vh [T_LEN * HDIM], g_vl [T_LEN * HDIM];
__device__ __nv_bfloat16 g_wqh[DM * DM],   g_wql[DM * DM];
__device__ __nv_bfloat16 g_woh[DM * DM],   g_wol[DM * DM];

// ================= helpers ==================================================
__device__ __forceinline__ uint32_t smem_u32(const void* p) {
    uint32_t a;
    asm("{ .reg .u64 t; cvta.to.shared.u64 t, %1; cvt.u32.u64 %0, t; }"
        : "=r"(a) : "l"(p));
    return a;
}
__device__ __forceinline__ void cp_async16(uint32_t saddr, const void* gaddr) {
    asm volatile("cp.async.cg.shared.global [%0], [%1], 16;"
                 :: "r"(saddr), "l"(gaddr));
}
__device__ __forceinline__ void cp_commit() {
    asm volatile("cp.async.commit_group;" ::: "memory");
}
__device__ __forceinline__ void cp_wait0() {
    asm volatile("cp.async.wait_group 0;" ::: "memory");
}
__device__ __forceinline__ void ldsm4(uint32_t* r, uint32_t addr) {
    asm volatile("ldmatrix.sync.aligned.m8n8.x4.shared.b16 {%0,%1,%2,%3}, [%4];"
                 : "=r"(r[0]), "=r"(r[1]), "=r"(r[2]), "=r"(r[3]) : "r"(addr));
}
__device__ __forceinline__ void ldsm2(uint32_t* r, uint32_t addr) {
    asm volatile("ldmatrix.sync.aligned.m8n8.x2.shared.b16 {%0,%1}, [%2];"
                 : "=r"(r[0]), "=r"(r[1]) : "r"(addr));
}
__device__ __forceinline__ void ldsm4t(uint32_t* r, uint32_t addr) {
    asm volatile("ldmatrix.sync.aligned.m8n8.x4.trans.shared.b16 {%0,%1,%2,%3}, [%4];"
                 : "=r"(r[0]), "=r"(r[1]), "=r"(r[2]), "=r"(r[3]) : "r"(addr));
}
__device__ __forceinline__ void mma16816(float* d, const uint32_t* a, const uint32_t* b) {
    asm volatile(
        "mma.sync.aligned.m16n8k16.row.col.f32.bf16.bf16.f32 "
        "{%0,%1,%2,%3}, {%4,%5,%6,%7}, {%8,%9}, {%0,%1,%2,%3};"
        : "+f"(d[0]), "+f"(d[1]), "+f"(d[2]), "+f"(d[3])
        : "r"(a[0]), "r"(a[1]), "r"(a[2]), "r"(a[3]), "r"(b[0]), "r"(b[1]));
}
__device__ __forceinline__ void mma16808(float* d, uint32_t a0, uint32_t a1, uint32_t b0) {
    asm volatile(
        "mma.sync.aligned.m16n8k8.row.col.f32.bf16.bf16.f32 "
        "{%0,%1,%2,%3}, {%4,%5}, {%6}, {%0,%1,%2,%3};"
        : "+f"(d[0]), "+f"(d[1]), "+f"(d[2]), "+f"(d[3])
        : "r"(a0), "r"(a1), "r"(b0));
}
__device__ __forceinline__ uint32_t pack_bf16x2(float lo, float hi) {
    uint32_t r;
    asm("cvt.rn.bf16x2.f32 %0, %1, %2;" : "=r"(r) : "f"(hi), "f"(lo));
    return r;
}

// ================= fp32 -> bf16 hi/lo conversion ============================
__global__ __launch_bounds__(256) void conv_hilo(const float4* __restrict__ src,
                                                 uint2* __restrict__ h,
                                                 uint2* __restrict__ l, int n4) {
    int i = blockIdx.x * 256 + threadIdx.x;
    if (i >= n4) return;
    float4 v = src[i];
    __nv_bfloat16 h0 = __float2bfloat16(v.x), h1 = __float2bfloat16(v.y);
    __nv_bfloat16 h2 = __float2bfloat16(v.z), h3 = __float2bfloat16(v.w);
    __nv_bfloat16 l0 = __float2bfloat16(v.x - __bfloat162float(h0));
    __nv_bfloat16 l1 = __float2bfloat16(v.y - __bfloat162float(h1));
    __nv_bfloat16 l2 = __float2bfloat16(v.z - __bfloat162float(h2));
    __nv_bfloat16 l3 = __float2bfloat16(v.w - __bfloat162float(h3));
    uint2 hv, lv;
    hv.x = (uint32_t)__bfloat16_as_ushort(h0) | ((uint32_t)__bfloat16_as_ushort(h1) << 16);
    hv.y = (uint32_t)__bfloat16_as_ushort(h2) | ((uint32_t)__bfloat16_as_ushort(h3) << 16);
    lv.x = (uint32_t)__bfloat16_as_ushort(l0) | ((uint32_t)__bfloat16_as_ushort(l1) << 16);
    lv.y = (uint32_t)__bfloat16_as_ushort(l2) | ((uint32_t)__bfloat16_as_ushort(l3) << 16);
    h[i] = hv;
    l[i] = lv;
}

// ================= tensor-core GEMM via mma.sync (bf16x3) ===================
#define TSTRIDE 80
#define TILE_BYTES (128 * TSTRIDE)
#define BUF_BYTES  (4 * TILE_BYTES)
#define GEMM_SMEM  (2 * BUF_BYTES)

__global__ __launch_bounds__(256) void gemm_mma(const __nv_bfloat16* __restrict__ Ah,
                                                const __nv_bfloat16* __restrict__ Al,
                                                const __nv_bfloat16* __restrict__ Bh,
                                                const __nv_bfloat16* __restrict__ Bl,
                                                float* __restrict__ C,
                                                __nv_bfloat16* __restrict__ Ch,
                                                __nv_bfloat16* __restrict__ Cl) {
    extern __shared__ char sm[];
    const uint32_t sbase = smem_u32(sm);
    const int tid = threadIdx.x;
    const int lane = tid & 31, wid = tid >> 5;
    const int m0 = blockIdx.y * 128;
    const int n0 = blockIdx.x * 128;
    const int wm = (wid >> 2) * 64;
    const int wn = (wid & 3) * 32;

    const __nv_bfloat16* gsrc[4] = {Ah, Al, Bh, Bl};

    float acc[4][4][4];
#pragma unroll
    for (int i = 0; i < 4; i++)
#pragma unroll
        for (int j = 0; j < 4; j++)
#pragma unroll
            for (int k = 0; k < 4; k++) acc[i][j][k] = 0.f;

    const int arow = wm + (lane & 15);
    const int akc  = (lane >> 4) << 3;
    const int brow = wn + (lane & 7) + ((lane >> 4) << 3);
    const int bkc  = ((lane >> 3) & 1) << 3;

    auto issue = [&](int c, int buf) {
#pragma unroll
        for (int T = 0; T < 4; T++) {
            const __nv_bfloat16* src = gsrc[T];
            const int rb = (T < 2) ? m0 : n0;
#pragma unroll
            for (int i = 0; i < 2; i++) {
                int idx = i * 256 + tid;
                int row = idx >> 2;
                int u   = idx & 3;
                uint32_t sa = sbase + buf * BUF_BYTES + T * TILE_BYTES + row * TSTRIDE + u * 16;
                cp_async16(sa, src + (size_t)(rb + row) * 1024 + c * 32 + u * 8);
            }
        }
        cp_commit();
    };

    issue(0, 0);

    for (int c = 0; c < 32; c++) {
        const int buf = c & 1;
        cp_wait0();
        __syncthreads();
        if (c + 1 < 32) issue(c + 1, buf ^ 1);

        const uint32_t base = sbase + buf * BUF_BYTES;
#pragma unroll
        for (int ks = 0; ks < 2; ks++) {
            uint32_t ah[4][4], al[4][4], bh[2][4], bl[2][4];
#pragma unroll
            for (int mt = 0; mt < 4; mt++) {
                uint32_t aa = base + (arow + mt * 16) * TSTRIDE + (ks * 16 + akc) * 2;
                ldsm4(ah[mt], aa);
                ldsm4(al[mt], aa + TILE_BYTES);
            }
#pragma unroll
            for (int np = 0; np < 2; np++) {
                uint32_t ba = base + 2 * TILE_BYTES + (brow + np * 16) * TSTRIDE + (ks * 16 + bkc) * 2;
                ldsm4(bh[np], ba);
                ldsm4(bl[np], ba + TILE_BYTES);
            }
#pragma unroll
            for (int mt = 0; mt < 4; mt++)
#pragma unroll
                for (int nt = 0; nt < 4; nt++) {
                    const uint32_t* ph = &bh[nt >> 1][(nt & 1) * 2];
                    const uint32_t* pl = &bl[nt >> 1][(nt & 1) * 2];
                    mma16816(acc[mt][nt], ah[mt], ph);
                    mma16816(acc[mt][nt], al[mt], ph);
                    mma16816(acc[mt][nt], ah[mt], pl);
                }
        }
        __syncthreads();
    }

    const int g = lane >> 2, t4 = lane & 3;
#pragma unroll
    for (int mt = 0; mt < 4; mt++)
#pragma unroll
        for (int nt = 0; nt < 4; nt++) {
            int r = m0 + wm + mt * 16 + g;
            int cc = n0 + wn + nt * 8 + t4 * 2;
#pragma unroll
            for (int half = 0; half < 2; half++) {
                int rr = r + half * 8;
                float v0 = acc[mt][nt][half * 2], v1 = acc[mt][nt][half * 2 + 1];
                *(float2*)(C + (size_t)rr * 1024 + cc) = make_float2(v0, v1);
                if (Ch) {
                    __nv_bfloat16 b0 = __float2bfloat16(v0), b1 = __float2bfloat16(v1);
                    __nv_bfloat16 c0 = __float2bfloat16(v0 - __bfloat162float(b0));
                    __nv_bfloat16 c1 = __float2bfloat16(v1 - __bfloat162float(b1));
                    *(uint32_t*)(Ch + (size_t)rr * 1024 + cc) =
                        (uint32_t)__bfloat16_as_ushort(b0) | ((uint32_t)__bfloat16_as_ushort(b1) << 16);
                    *(uint32_t*)(Cl + (size_t)rr * 1024 + cc) =
                        (uint32_t)__bfloat16_as_ushort(c0) | ((uint32_t)__bfloat16_as_ushort(c1) << 16);
                }
            }
        }
}

// ---------------- small projections: K, V, G ------------------
__global__ __launch_bounds__(256) void proj_small(const float* __restrict__ X,
                                                  const float* __restrict__ Wk,
                                                  const float* __restrict__ Wv,
                                                  const float* __restrict__ Wg) {
    const float* B; float* C; int N;
    __nv_bfloat16 *H = nullptr, *L = nullptr;
    if (blockIdx.x == 0)      { B = Wk; C = g_k; N = 64; H = g_kh; L = g_kl; }
    else if (blockIdx.x == 1) { B = Wv; C = g_v; N = 64; H = g_vh; L = g_vl; }
    else                      { B = Wg; C = g_g; N = 48; }

    __shared__ float As[16][68];
    __shared__ float Bs[16][68];
    const int tid = threadIdx.x;
    const int m0 = blockIdx.y * 64;
    const int lr = tid >> 2;
    const int lc = (tid & 3) << 2;
    const int tx = tid & 15, ty = tid >> 4;

    float acc[4][4];
#pragma unroll
    for (int i = 0; i < 4; i++)
#pragma unroll
        for (int j = 0; j < 4; j++) acc[i][j] = 0.f;

    for (int k0 = 0; k0 < 1024; k0 += 16) {
        float4 a = *(const float4*)(X + (size_t)(m0 + lr) * 1024 + k0 + lc);
        float4 b = (lr < N) ? *(const float4*)(B + (size_t)lr * 1024 + k0 + lc)
                            : make_float4(0.f, 0.f, 0.f, 0.f);
        __syncthreads();
        As[lc + 0][lr] = a.x; As[lc + 1][lr] = a.y;
        As[lc + 2][lr] = a.z; As[lc + 3][lr] = a.w;
        Bs[lc + 0][lr] = b.x; Bs[lc + 1][lr] = b.y;
        Bs[lc + 2][lr] = b.z; Bs[lc + 3][lr] = b.w;
        __syncthreads();
#pragma unroll
        for (int kk = 0; kk < 16; kk++) {
            float4 a4 = *(const float4*)&As[kk][ty * 4];
            float4 b4 = *(const float4*)&Bs[kk][tx * 4];
            float ar[4] = {a4.x, a4.y, a4.z, a4.w};
            float br[4] = {b4.x, b4.y, b4.z, b4.w};
#pragma unroll
            for (int i = 0; i < 4; i++)
#pragma unroll
                for (int j = 0; j < 4; j++) acc[i][j] += ar[i] * br[j];
        }
    }
#pragma unroll
    for (int i = 0; i < 4; i++) {
        int row = m0 + ty * 4 + i;
#pragma unroll
        for (int j = 0; j < 4; j++) {
            int col = tx * 4 + j;
            if (col < N) {
                float v = acc[i][j];
                C[(size_t)row * N + col] = v;
                if (H) {
                    __nv_bfloat16 bh = __float2bfloat16(v);
                    H[(size_t)row * 64 + col] = bh;
                    L[(size_t)row * 64 + col] = __float2bfloat16(v - __bfloat162float(bh));
                }
            }
        }
    }
}

// ---------------- mean-pool K,V ---------------------------------------------
__global__ void pool_kv() {
    int c = blockIdx.x, d = threadIdx.x;
    float sk = 0.f, sv = 0.f;
    for (int i = 0; i < 64; i++) {
        sk += g_k[(size_t)(c * 64 + i) * 64 + d];
        sv += g_v[(size_t)(c * 64 + i) * 64 + d];
    }
    g_kc[c * 64 + d] = sk * (1.f / 64.f);
    g_vc[c * 64 + d] = sv * (1.f / 64.f);
}

// ---------------- compressed attention + top-k selection --------------------
__global__ __launch_bounds__(128) void cmp_kernel() {
    __shared__ float sq[1024];
    __shared__ float skc[NB * 64];
    __shared__ float svc[NB * 64];
    __shared__ float sp[NHEAD * NB];
    __shared__ float simp[NB];

    const int t = blockIdx.x, tid = threadIdx.x;
    for (int i = tid; i < 256; i += 128)
        ((float4*)sq)[i] = ((const float4*)(g_q + (size_t)t * 1024))[i];
    for (int i = tid; i < 512; i += 128) {
        ((float4*)skc)[i] = ((const float4*)g_kc)[i];
        ((float4*)svc)[i] = ((const float4*)g_vc)[i];
    }
    __syncthreads();

    const int cur = t >> 6;
    const int nvis = (t + 1) >> 6;
    const float scale = 0.125f;

    for (int idx = tid; idx < NHEAD * NB; idx += 128) {
        int h = idx >> 5, c = idx & 31;
        float s;
        if (c < nvis) {
            const float4* qa = (const float4*)(sq + h * 64);
            const float4* ka = (const float4*)(skc + c * 64);
            s = 0.f;
#pragma unroll
            for (int i = 0; i < 16; i++) {
                float4 x = qa[i], y = ka[i];
                s += x.x * y.x + x.y * y.y + x.z * y.z + x.w * y.w;
            }
            s *= scale;
        } else s = NEGV;
        sp[idx] = s;
    }
    __syncthreads();

    if (tid < NHEAD) {
        float* row = sp + tid * NB;
        if (nvis == 0) {
            for (int c = 0; c < NB; c++) row[c] = 0.f;
        } else {
            float m = -INFINITY;
            for (int c = 0; c < nvis; c++) m = fmaxf(m, row[c]);
            float sum = 0.f;
            for (int c = 0; c < nvis; c++) { float e = __expf(row[c] - m); row[c] = e; sum += e; }
            float inv = 1.f / sum;
            for (int c = 0; c < nvis; c++) row[c] *= inv;
            for (int c = nvis; c < NB; c++) row[c] = 0.f;
        }
    }
    __syncthreads();

    for (int idx = tid; idx < NHEAD * HDIM; idx += 128) {
        int h = idx >> 6, d = idx & 63;
        float o = 0.f;
        for (int c = 0; c < nvis; c++) o += sp[h * NB + c] * svc[c * 64 + d];
        g_ocmp[(size_t)t * 1024 + idx] = o;
    }

    if (tid < NB) {
        int c = tid;
        float im;
        if (c == 0 || c == cur) im = INFINITY;
        else if (c <= cur) {
            im = 0.f;
            for (int h = 0; h < NHEAD; h++) im += sp[h * NB + c];
        } else im = NEGV;
        simp[c] = im;
    }
    __syncthreads();

    if (tid == 0) {
        unsigned used = 0;
        for (int s = 0; s < SSEL; s++) {
            float bv = -INFINITY; int bc = 0;
            for (int c = 0; c < NB; c++)
                if (!((used >> c) & 1u) && simp[c] > bv) { bv = simp[c]; bc = c; }
            used |= (1u << bc);
            g_blk[t * SSEL + s] = bc;
        }
    }
}

// ============ flash-style selected attention (tensor cores, bf16x3) =========
// one CTA per token, 8 warps. warp w owns token-octet w of each block.
// smem: sQh @0 (16x144), sQl @2304, stages @4608: 2 x {Kh,Kl,Vh,Vl} each 64x144
#define QTILE 2304
#define STAGE0 4608
#define STAGEB 36864          // 4 * 9216
#define KVTILE 9216           // 64 rows * 144B
#define SLC_SMEM (4608 + 2 * STAGEB)   // 78336

__global__ __launch_bounds__(256, 2) void slc_flash() {
    extern __shared__ char smc[];
    const uint32_t sb0 = smem_u32(smc);
    const int t = blockIdx.x, tid = threadIdx.x;
    const int lane = tid & 31, w = tid >> 5;

    // load Q (hi/lo) into smem, 1x16B per thread
    {
        int tile = tid >> 7;
        int idx = tid & 127;
        int row = idx >> 3, u = idx & 7;
        const uint4* src = (const uint4*)((tile ? g_ql : g_qh) + (size_t)t * 1024);
        *(uint4*)(smc + tile * QTILE + row * 144 + u * 16) = src[idx];
    }

    auto issue = [&](int kb, int stage) {
        int sb = g_blk[t * SSEL + kb];
        const __nv_bfloat16* gp0 = g_kh; const __nv_bfloat16* gp1 = g_kl;
        const __nv_bfloat16* gp2 = g_vh; const __nv_bfloat16* gp3 = g_vl;
        uint32_t base = sb0 + STAGE0 + stage * STAGEB;
#pragma unroll
        for (int i = 0; i < 8; i++) {
            int cid = i * 256 + tid;
            int tile = cid >> 9, r = (cid >> 3) & 63, u = cid & 7;
            const __nv_bfloat16* gp = (tile == 0) ? gp0 : (tile == 1) ? gp1 : (tile == 2) ? gp2 : gp3;
            cp_async16(base + tile * KVTILE + r * 144 + u * 16,
                       gp + (size_t)(sb * 64 + r) * 64 + u * 8);
        }
        cp_commit();
    };

    issue(0, 0);
    __syncthreads();

    // preload Q fragments (A, m16k16 per kstep)
    uint32_t qfh[4][4], qfl[4][4];
    {
        uint32_t qa = sb0 + (lane & 15) * 144 + ((lane >> 4) << 4);
#pragma unroll
        for (int ks = 0; ks < 4; ks++) {
            ldsm4(qfh[ks], qa + ks * 32);
            ldsm4(qfl[ks], qa + QTILE + ks * 32);
        }
    }

    float ov[8][4];
#pragma unroll
    for (int j = 0; j < 8; j++)
#pragma unroll
        for (int k = 0; k < 4; k++) ov[j][k] = 0.f;
    float m0r = NEGS, m1r = NEGS, s0r = 0.f, s1r = 0.f;
    const float scale = 0.125f;

    for (int kb = 0; kb < SSEL; kb++) {
        const int stage = kb & 1;
        cp_wait0();
        __syncthreads();
        if (kb + 1 < SSEL) issue(kb + 1, stage ^ 1);

        const uint32_t base = sb0 + STAGE0 + stage * STAGEB;
        const int sb = g_blk[t * SSEL + kb];

        // ---- QK (bf16x3) ----
        float d[4] = {0.f, 0.f, 0.f, 0.f};
        uint32_t kaddr = base + (w * 8 + (lane & 7)) * 144 + ((lane >> 3) & 1) * 16;
#pragma unroll
        for (int ks = 0; ks < 4; ks++) {
            uint32_t kh2[2], kl2[2];
            ldsm2(kh2, kaddr + ks * 32);
            ldsm2(kl2, kaddr + KVTILE + ks * 32);
            mma16816(d, qfh[ks], kh2);
            mma16816(d, qfl[ks], kh2);
            mma16816(d, qfh[ks], kl2);
        }

        // ---- scale + mask ----
        int tok = sb * 64 + w * 8 + ((lane & 3) << 1);
        bool v0 = tok <= t, v1 = tok + 1 <= t;
        d[0] = v0 ? d[0] * scale : NEGS;
        d[1] = v1 ? d[1] * scale : NEGS;
        d[2] = v0 ? d[2] * scale : NEGS;
        d[3] = v1 ? d[3] * scale : NEGS;

        // ---- online softmax (per head row, quad reduce) ----
        float bm0 = fmaxf(d[0], d[1]), bm1 = fmaxf(d[2], d[3]);
        bm0 = fmaxf(bm0, __shfl_xor_sync(0xffffffffu, bm0, 1));
        bm0 = fmaxf(bm0, __shfl_xor_sync(0xffffffffu, bm0, 2));
        bm1 = fmaxf(bm1, __shfl_xor_sync(0xffffffffu, bm1, 1));
        bm1 = fmaxf(bm1, __shfl_xor_sync(0xffffffffu, bm1, 2));
        float mn0 = fmaxf(m0r, bm0), mn1 = fmaxf(m1r, bm1);
        float a0 = __expf(m0r - mn0), a1 = __expf(m1r - mn1);
        m0r = mn0; m1r = mn1;
        float p0 = __expf(d[0] - mn0), p1 = __expf(d[1] - mn0);
        float p2 = __expf(d[2] - mn1), p3 = __expf(d[3] - mn1);
        float ps0 = p0 + p1, ps1 = p2 + p3;
        ps0 += __shfl_xor_sync(0xffffffffu, ps0, 1);
        ps0 += __shfl_xor_sync(0xffffffffu, ps0, 2);
        ps1 += __shfl_xor_sync(0xffffffffu, ps1, 1);
        ps1 += __shfl_xor_sync(0xffffffffu, ps1, 2);
        s0r = s0r * a0 + ps0;
        s1r = s1r * a1 + ps1;
#pragma unroll
        for (int j = 0; j < 8; j++) {
            ov[j][0] *= a0; ov[j][1] *= a0;
            ov[j][2] *= a1; ov[j][3] *= a1;
        }

        // ---- pack P to bf16 hi/lo A-fragments ----
        __nv_bfloat16 b0 = __float2bfloat16(p0), b1 = __float2bfloat16(p1);
        __nv_bfloat16 b2 = __float2bfloat16(p2), b3 = __float2bfloat16(p3);
        uint32_t ah0 = (uint32_t)__bfloat16_as_ushort(b0) | ((uint32_t)__bfloat16_as_ushort(b1) << 16);
        uint32_t ah1 = (uint32_t)__bfloat16_as_ushort(b2) | ((uint32_t)__bfloat16_as_ushort(b3) << 16);
        uint32_t al0 = pack_bf16x2(p0 - __bfloat162float(b0), p1 - __bfloat162float(b1));
        uint32_t al1 = pack_bf16x2(p2 - __bfloat162float(b2), p3 - __bfloat162float(b3));

        // ---- PV (bf16x3) ----
        uint32_t vh[8], vl[8];
        uint32_t vaddr = base + 2 * KVTILE + (w * 8 + (lane & 7)) * 144 + (lane >> 3) * 16;
        ldsm4t(vh, vaddr);        ldsm4t(vh + 4, vaddr + 64);
        ldsm4t(vl, vaddr + KVTILE); ldsm4t(vl + 4, vaddr + KVTILE + 64);
#pragma unroll
        for (int j = 0; j < 8; j++) {
            mma16808(ov[j], ah0, ah1, vh[j]);
            mma16808(ov[j], al0, al1, vh[j]);
            mma16808(ov[j], ah0, ah1, vl[j]);
        }
    }

    // ---- cross-warp merge via smem (stage0 region is free) ----
    const int g = lane >> 2;
    float* sM   = (float*)(smc + STAGE0);          // [8][16]
    float* sSum = (float*)(smc + STAGE0 + 512);    // [8][16]
    float* sO   = (float*)(smc + STAGE0 + 1024);   // [8][16][64]
    if ((lane & 3) == 0) {
        sM[w * 16 + g]       = m0r;
        sM[w * 16 + g + 8]   = m1r;
        sSum[w * 16 + g]     = s0r;
        sSum[w * 16 + g + 8] = s1r;
    }
#pragma unroll
    for (int j = 0; j < 8; j++) {
        int col = j * 8 + (lane & 3) * 2;
        *(float2*)(sO + (w * 16 + g) * 64 + col)     = make_float2(ov[j][0], ov[j][1]);
        *(float2*)(sO + (w * 16 + g + 8) * 64 + col) = make_float2(ov[j][2], ov[j][3]);
    }
    __syncthreads();

    // ---- final combine: 256 threads, (head, 4 dims) each ----
    {
        int h = tid >> 4;
        int dg = (tid & 15) * 4;
        float M = -INFINITY;
#pragma unroll
        for (int ww = 0; ww < 8; ww++) M = fmaxf(M, sM[ww * 16 + h]);
        float4 o = make_float4(0.f, 0.f, 0.f, 0.f);
        float den = 0.f;
#pragma unroll
        for (int ww = 0; ww < 8; ww++) {
            float e = __expf(sM[ww * 16 + h] - M);
            den += e * sSum[ww * 16 + h];
            float4 x = *(float4*)(sO + (ww * 16 + h) * 64 + dg);
            o.x += e * x.x; o.y += e * x.y; o.z += e * x.z; o.w += e * x.w;
        }
        float inv = 1.f / den;
        float gc = 1.f / (1.f + __expf(-g_g[t * 48 + h * 3]));
        float gs = 1.f / (1.f + __expf(-g_g[t * 48 + h * 3 + 1]));
        float4 oc = *(const float4*)(g_ocmp + (size_t)t * 1024 + h * 64 + dg);
        float c0 = o.x * inv * gs + oc.x * gc;
        float c1 = o.y * inv * gs + oc.y * gc;
        float c2 = o.z * inv * gs + oc.z * gc;
        float c3 = o.w * inv * gs + oc.w * gc;
        __nv_bfloat16 h0 = __float2bfloat16(c0), h1 = __float2bfloat16(c1);
        __nv_bfloat16 h2 = __float2bfloat16(c2), h3 = __float2bfloat16(c3);
        uint2 hv, lv;
        hv.x = (uint32_t)__bfloat16_as_ushort(h0) | ((uint32_t)__bfloat16_as_ushort(h1) << 16);
        hv.y = (uint32_t)__bfloat16_as_ushort(h2) | ((uint32_t)__bfloat16_as_ushort(h3) << 16);
        lv.x = pack_bf16x2(c0 - __bfloat162float(h0), c1 - __bfloat162float(h1));
        lv.y = pack_bf16x2(c2 - __bfloat162float(h2), c3 - __bfloat162float(h3));
        *(uint2*)(g_ch + (size_t)t * 1024 + h * 64 + dg) = hv;
        *(uint2*)(g_cl + (size_t)t * 1024 + h * 64 + dg) = lv;
    }
}

// ---------------- launch ----------------------------------------------------
extern "C" void kernel_launch(void* const* d_in, const int* in_sizes, int n_in,
                              void* d_out, int out_size) {
    const float* x  = (const float*)d_in[0];
    const float* Wq = (const float*)d_in[1];
    const float* Wk = (const float*)d_in[2];
    const float* Wv = (const float*)d_in[3];
    const float* Wg = (const float*)d_in[4];
    const float* Wo = (const float*)d_in[5];
    float* out = (float*)d_out;

    void *pq, *pxh, *pxl, *pch, *pcl, *pwqh, *pwql, *pwoh, *pwol, *pqh, *pql;
    cudaGetSymbolAddress(&pq, g_q);
    cudaGetSymbolAddress(&pxh, g_xh);   cudaGetSymbolAddress(&pxl, g_xl);
    cudaGetSymbolAddress(&pch, g_ch);   cudaGetSymbolAddress(&pcl, g_cl);
    cudaGetSymbolAddress(&pwqh, g_wqh); cudaGetSymbolAddress(&pwql, g_wql);
    cudaGetSymbolAddress(&pwoh, g_woh); cudaGetSymbolAddress(&pwol, g_wol);
    cudaGetSymbolAddress(&pqh, g_qh);   cudaGetSymbolAddress(&pql, g_ql);

    cudaFuncSetAttribute(gemm_mma, cudaFuncAttributeMaxDynamicSharedMemorySize, GEMM_SMEM);
    cudaFuncSetAttribute(slc_flash, cudaFuncAttributeMaxDynamicSharedMemorySize, SLC_SMEM);

    conv_hilo<<<(T_LEN * DM / 4 + 255) / 256, 256>>>((const float4*)x, (uint2*)pxh, (uint2*)pxl, T_LEN * DM / 4);
    conv_hilo<<<(DM * DM / 4 + 255) / 256, 256>>>((const float4*)Wq, (uint2*)pwqh, (uint2*)pwql, DM * DM / 4);
    conv_hilo<<<(DM * DM / 4 + 255) / 256, 256>>>((const float4*)Wo, (uint2*)pwoh, (uint2*)pwol, DM * DM / 4);

    // Q = x @ Wq^T  (also emits qh/ql bf16)
    gemm_mma<<<dim3(8, 16), 256, GEMM_SMEM>>>((const __nv_bfloat16*)pxh, (const __nv_bfloat16*)pxl,
                                              (const __nv_bfloat16*)pwqh, (const __nv_bfloat16*)pwql,
                                              (float*)pq, (__nv_bfloat16*)pqh, (__nv_bfloat16*)pql);
    proj_small<<<dim3(3, 32), 256>>>(x, Wk, Wv, Wg);
    pool_kv<<<NB, 64>>>();
    cmp_kernel<<<T_LEN, 128>>>();
    slc_flash<<<T_LEN, 256, SLC_SMEM>>>();

    // out = comb @ Wo^T
    gemm_mma<<<dim3(8, 16), 256, GEMM_SMEM>>>((const __nv_bfloat16*)pch, (const __nv_bfloat16*)pcl,
                                              (const __nv_bfloat16*)pwoh, (const __nv_bfloat16*)pwol,
                                              out, nullptr, nullptr);
}